// round 4
// baseline (speedup 1.0000x reference)
#include <cuda_runtime.h>
#include <math.h>

#define NRES 768
#define DN   256
#define DE   128
#define EF   30
#define KP   32            // padded K for MMA
#define JTILE 64
#define TILES 4            // j-tiles per block
typedef unsigned long long ull;

// ---- output layout (floats), concatenation of the reference tuple ----
#define NODE_OFF 0ULL
#define EDGE_OFF (768ULL * 256ULL)                       // 196608
#define IDX_OFF  (EDGE_OFF + 768ULL * 768ULL * 128ULL)   // 75694080
#define MI_OFF   (IDX_OFF + 768ULL * 768ULL)             // 76283904
#define MIJ_OFF  (MI_OFF + 768ULL)                       // 76284672

// scratch: per-residue frames R (row-major 3x3)
__device__ float g_R[NRES * 9];

__device__ __forceinline__ float3 ld3(const float* p) { return make_float3(p[0], p[1], p[2]); }
__device__ __forceinline__ float3 vsub(float3 a, float3 b) { return make_float3(a.x - b.x, a.y - b.y, a.z - b.z); }
__device__ __forceinline__ float  vdot(float3 a, float3 b) { return a.x * b.x + a.y * b.y + a.z * b.z; }
__device__ __forceinline__ float3 vcross(float3 a, float3 b) {
    return make_float3(a.y * b.z - a.z * b.y, a.z * b.x - a.x * b.z, a.x * b.y - a.y * b.x);
}
__device__ __forceinline__ float  vnorm(float3 a) { return sqrtf(vdot(a, a) + 1e-8f); }
__device__ __forceinline__ float3 vunit(float3 a) { float r = 1.0f / vnorm(a); return make_float3(a.x * r, a.y * r, a.z * r); }

// tf32 round (rna) -> fp32 bit pattern with low mantissa cleared
__device__ __forceinline__ unsigned tf32r(float x) {
    unsigned r; asm("cvt.rna.tf32.f32 %0, %1;" : "=r"(r) : "f"(x)); return r;
}

// m16n8k8 tf32 MMA, D += A*B
__device__ __forceinline__ void mma_tf32(float d[4], const unsigned a[4], const unsigned b[2]) {
    asm volatile(
        "mma.sync.aligned.m16n8k8.row.col.f32.tf32.tf32.f32 "
        "{%0,%1,%2,%3}, {%4,%5,%6,%7}, {%8,%9}, {%0,%1,%2,%3};"
        : "+f"(d[0]), "+f"(d[1]), "+f"(d[2]), "+f"(d[3])
        : "r"(a[0]), "r"(a[1]), "r"(a[2]), "r"(a[3]), "r"(b[0]), "r"(b[1]));
}

// ============================================================================
// Node kernel (tiny)
// ============================================================================
__global__ void __launch_bounds__(256) node_kernel(
    const float* __restrict__ X, const int* __restrict__ C,
    const float* __restrict__ aux, const float* __restrict__ Wn,
    const float* __restrict__ bn, float* __restrict__ out)
{
    __shared__ float sfeat[7];
    __shared__ float smask;
    const int n = blockIdx.x;

    if (threadIdx.x == 0) {
        const float* xp = X + n * 12;
        float3 Na = ld3(xp), Ca = ld3(xp + 3), Cc = ld3(xp + 6), Ox = ld3(xp + 9);

        float d1 = logf(vnorm(vsub(Ca, Na)) + 0.001f);
        float d2 = logf(vnorm(vsub(Cc, Ca)) + 0.001f);
        float d3 = logf(vnorm(vsub(Ox, Cc)) + 0.001f);
        float a1 = vdot(vunit(vsub(Na, Ca)), vunit(vsub(Cc, Ca)));
        float a2 = vdot(vunit(vsub(Ca, Cc)), vunit(vsub(Ox, Cc)));

        float3 b0 = vsub(Ca, Na), b1 = vsub(Cc, Ca), b2 = vsub(Ox, Cc);
        float3 n1 = vcross(b0, b1), n2 = vcross(b1, b2);
        float3 ub1 = vunit(b1);
        float3 m1 = vcross(n1, ub1);
        float xx = vdot(n1, n2), yy = vdot(m1, n2);
        float r = sqrtf(xx * xx + yy * yy + 1e-8f);

        sfeat[0] = d1; sfeat[1] = d2; sfeat[2] = d3;
        sfeat[3] = a1; sfeat[4] = a2;
        sfeat[5] = yy / r; sfeat[6] = xx / r;

        float mi = (C[n] > 0) ? 1.0f : 0.0f;
        smask = mi;
        out[MI_OFF + n] = mi;

        float3 e1 = ub1;
        float3 v  = vunit(vsub(Na, Ca));
        float d  = vdot(v, e1);
        float3 w = make_float3(v.x - d * e1.x, v.y - d * e1.y, v.z - d * e1.z);
        float3 e2 = vunit(w);
        float3 e3 = vcross(e1, e2);
        float* rp = g_R + n * 9;
        rp[0] = e1.x; rp[1] = e1.y; rp[2] = e1.z;
        rp[3] = e2.x; rp[4] = e2.y; rp[5] = e2.z;
        rp[6] = e3.x; rp[7] = e3.y; rp[8] = e3.z;
    }
    __syncthreads();

    const int c = threadIdx.x;
    float acc = bn[c];
#pragma unroll
    for (int k = 0; k < 7; k++) acc = fmaf(sfeat[k], Wn[k * DN + c], acc);
    float mi = smask;
    out[NODE_OFF + (size_t)n * DN + c] = mi * (acc + aux[(size_t)n * DN + c]);
}

// ============================================================================
// Edge kernel: 3xTF32 MMA, double-buffered pipeline, 4-threads-per-edge
// feature computation so all 256 threads work in both phases.
// ============================================================================
struct EdgeCtx {
    unsigned* sAh; unsigned* sAl;   // [2][64*36] each
    float* smij;                    // [2][64]
    const float* sXi; const float* sRi;
    float sMi; int sCi;
};

__device__ __forceinline__ void stsplit(unsigned* h, unsigned* l, int idx, float v) {
    unsigned hi = tf32r(v);
    h[idx] = hi;
    l[idx] = tf32r(v - __uint_as_float(hi));
}

__device__ __forceinline__ void compute_features(
    const EdgeCtx& cx, int buf, int i, int jbase, int tid,
    const float* __restrict__ X, const int* __restrict__ C,
    float* __restrict__ out)
{
    const int e = tid >> 2;      // edge within tile
    const int r = tid & 3;       // role
    const int j = jbase + e;

    unsigned* Ah = cx.sAh + buf * (64 * 36);
    unsigned* Al = cx.sAl + buf * (64 * 36);

    float xj[12];
#pragma unroll
    for (int q = 0; q < 12; q++) xj[q] = X[j * 12 + q];

    // D row r: f[r*4+q]
    const float xix = cx.sXi[3 * r + 0], xiy = cx.sXi[3 * r + 1], xiz = cx.sXi[3 * r + 2];
#pragma unroll
    for (int q = 0; q < 4; q++) {
        float dx = xix - xj[3 * q + 0];
        float dy = xiy - xj[3 * q + 1];
        float dz = xiz - xj[3 * q + 2];
        float d2 = dx * dx + dy * dy + dz * dz;
        stsplit(Ah, Al, e * 36 + r * 4 + q, logf(sqrtf(d2 + 1e-8f) + 0.01f));
    }

    if (r < 3) {
        // Rrel row r: needs all of R_j
        float rj[9];
#pragma unroll
        for (int q = 0; q < 9; q++) rj[q] = g_R[j * 9 + q];
        const float a0 = cx.sRi[3 * r + 0], a1 = cx.sRi[3 * r + 1], a2 = cx.sRi[3 * r + 2];
#pragma unroll
        for (int q = 0; q < 3; q++) {
            float v = a0 * rj[3 * q + 0] + a1 * rj[3 * q + 1] + a2 * rj[3 * q + 2];
            stsplit(Ah, Al, e * 36 + 16 + r * 3 + q, v);
        }
    } else {
        // trel, same_chain, sep, masks
        float dtx = xj[3] - cx.sXi[3], dty = xj[4] - cx.sXi[4], dtz = xj[5] - cx.sXi[5];
        float t0 = cx.sRi[0] * dtx + cx.sRi[1] * dty + cx.sRi[2] * dtz;
        float t1 = cx.sRi[3] * dtx + cx.sRi[4] * dty + cx.sRi[5] * dtz;
        float t2 = cx.sRi[6] * dtx + cx.sRi[7] * dty + cx.sRi[8] * dtz;
        float rn = rsqrtf(t0 * t0 + t1 * t1 + t2 * t2 + 1e-8f);
        stsplit(Ah, Al, e * 36 + 25, t0 * rn);
        stsplit(Ah, Al, e * 36 + 26, t1 * rn);
        stsplit(Ah, Al, e * 36 + 27, t2 * rn);
        int cj = C[j];
        stsplit(Ah, Al, e * 36 + 28, (cx.sCi == cj) ? 1.0f : 0.0f);
        int dsep = j - i; dsep = min(32, max(-32, dsep));
        stsplit(Ah, Al, e * 36 + 29, (float)dsep * (1.0f / 32.0f));

        float mij = cx.sMi * ((cj > 0) ? 1.0f : 0.0f);
        cx.smij[buf * 64 + e] = mij;
        out[IDX_OFF + (size_t)i * NRES + j] = (float)j;
        out[MIJ_OFF + (size_t)i * NRES + j] = mij;
    }
}

__global__ void __launch_bounds__(256, 2) edge_kernel(
    const float* __restrict__ X, const int* __restrict__ C,
    const float* __restrict__ aux, const float* __restrict__ We,
    const float* __restrict__ be, float* __restrict__ out)
{
    extern __shared__ __align__(16) unsigned char dsm[];
    unsigned* sAh = (unsigned*)dsm;                 // [2][64*36]
    unsigned* sAl = sAh + 2 * 64 * 36;              // [2][64*36]
    unsigned* sBh = sAl + 2 * 64 * 36;              // [128][36]  (c-major)
    unsigned* sBl = sBh + 128 * 36;                 // [128][36]
    float*    sb   = (float*)(sBl + 128 * 36);      // [128]
    float*    smij = sb + DE;                       // [2][64]

    __shared__ float sXi[12];
    __shared__ float sRi[9];
    __shared__ float sMiS;
    __shared__ int   sCiS;

    const int i   = blockIdx.y;
    const int tid = threadIdx.x;
    const int lane = tid & 31, warp = tid >> 5;
    const int gid = lane >> 2, tg = lane & 3;
    const int wm = warp & 1;       // 2 m-blocks of 32 edges
    const int wn = warp >> 1;      // 4 n-blocks of 32 channels

    // ---- one-time staging: split weights to tf32 hi/lo, transposed [c][k] ----
    for (int t = tid; t < KP * DE; t += 256) {
        int k = t >> 7, c = t & 127;
        float w = (k < EF) ? We[k * DE + c] : 0.0f;
        unsigned hi = tf32r(w);
        sBh[c * 36 + k] = hi;
        sBl[c * 36 + k] = tf32r(w - __uint_as_float(hi));
    }
    if (tid < DE) sb[tid] = be[tid];
    if (tid >= 128 && tid < 140) sXi[tid - 128] = X[i * 12 + (tid - 128)];
    if (tid >= 144 && tid < 153) sRi[tid - 144] = g_R[i * 9 + (tid - 144)];
    if (tid == 160) { int ci = C[i]; sCiS = ci; sMiS = (ci > 0) ? 1.0f : 0.0f; }
    // zero pad rows k=30,31 in both A buffers (never rewritten)
    if (tid < 64) {
#pragma unroll
        for (int b = 0; b < 2; b++) {
            sAh[b * 64 * 36 + tid * 36 + 30] = 0u; sAh[b * 64 * 36 + tid * 36 + 31] = 0u;
            sAl[b * 64 * 36 + tid * 36 + 30] = 0u; sAl[b * 64 * 36 + tid * 36 + 31] = 0u;
        }
    }
    __syncthreads();

    EdgeCtx cx{sAh, sAl, smij, sXi, sRi, sMiS, sCiS};

    const int jbase0 = blockIdx.x * TILES * JTILE;

    // prologue: features for tile 0
    compute_features(cx, 0, i, jbase0, tid, X, C, out);
    __syncthreads();

    for (int t = 0; t < TILES; t++) {
        const int buf = t & 1;
        const int jbase = jbase0 + t * JTILE;

        // overlap: features for next tile into the other buffer
        if (t + 1 < TILES)
            compute_features(cx, buf ^ 1, i, jbase + JTILE, tid, X, C, out);

        const unsigned* Ah = sAh + buf * (64 * 36);
        const unsigned* Al = sAl + buf * (64 * 36);

        // ---- 3xTF32 MMA. warp patch = 32 edges x 32 channels ----
        float acc[2][4][4] = {};
#pragma unroll
        for (int kt = 0; kt < 4; kt++) {
            const int k0 = kt * 8 + tg;
            unsigned ah[2][4], al[2][4];
#pragma unroll
            for (int m = 0; m < 2; m++) {
                const int e = wm * 32 + m * 16 + gid;
                ah[m][0] = Ah[e * 36 + k0];
                ah[m][1] = Ah[(e + 8) * 36 + k0];
                ah[m][2] = Ah[e * 36 + k0 + 4];
                ah[m][3] = Ah[(e + 8) * 36 + k0 + 4];
                al[m][0] = Al[e * 36 + k0];
                al[m][1] = Al[(e + 8) * 36 + k0];
                al[m][2] = Al[e * 36 + k0 + 4];
                al[m][3] = Al[(e + 8) * 36 + k0 + 4];
            }
            unsigned bh[4][2], bl[4][2];
#pragma unroll
            for (int n = 0; n < 4; n++) {
                const int c = wn * 32 + n * 8 + gid;
                bh[n][0] = sBh[c * 36 + k0];
                bh[n][1] = sBh[c * 36 + k0 + 4];
                bl[n][0] = sBl[c * 36 + k0];
                bl[n][1] = sBl[c * 36 + k0 + 4];
            }
#pragma unroll
            for (int m = 0; m < 2; m++)
#pragma unroll
                for (int n = 0; n < 4; n++) {
                    mma_tf32(acc[m][n], ah[m], bh[n]);
                    mma_tf32(acc[m][n], ah[m], bl[n]);
                    mma_tf32(acc[m][n], al[m], bh[n]);
                }
        }

        // ---- epilogue: + bias + aux, * mij, streaming float2 stores ----
#pragma unroll
        for (int m = 0; m < 2; m++) {
            const int el0 = wm * 32 + m * 16 + gid;
            const int el1 = el0 + 8;
            const float mj0 = smij[buf * 64 + el0];
            const float mj1 = smij[buf * 64 + el1];
            const int j0 = jbase + el0, j1 = jbase + el1;
#pragma unroll
            for (int n = 0; n < 4; n++) {
                const int c = wn * 32 + n * 8 + 2 * tg;
                float2 bv = *(const float2*)&sb[c];
                size_t base0 = ((size_t)i * NRES + j0) * DE + c;
                size_t base1 = ((size_t)i * NRES + j1) * DE + c;
                float2 a0 = __ldcs((const float2*)&aux[base0]);
                float2 a1 = __ldcs((const float2*)&aux[base1]);
                float2 o0, o1;
                o0.x = mj0 * (acc[m][n][0] + bv.x + a0.x);
                o0.y = mj0 * (acc[m][n][1] + bv.y + a0.y);
                o1.x = mj1 * (acc[m][n][2] + bv.x + a1.x);
                o1.y = mj1 * (acc[m][n][3] + bv.y + a1.y);
                __stcs((float2*)&out[EDGE_OFF + base0], o0);
                __stcs((float2*)&out[EDGE_OFF + base1], o1);
            }
        }
        __syncthreads();   // buffer handoff
    }
}

#define EDGE_DSM ((2 * 64 * 36 * 2 + 2 * 128 * 36) * 4 + (DE + 2 * JTILE) * 4)

extern "C" void kernel_launch(void* const* d_in, const int* in_sizes, int n_in,
                              void* d_out, int out_size)
{
    const float* X        = (const float*)d_in[0];
    const int*   C        = (const int*)  d_in[1];
    const float* node_aux = (const float*)d_in[2];
    const float* edge_aux = (const float*)d_in[3];
    const float* W_node   = (const float*)d_in[4];
    const float* b_node   = (const float*)d_in[5];
    const float* W_edge   = (const float*)d_in[6];
    const float* b_edge   = (const float*)d_in[7];
    float* out = (float*)d_out;

    cudaFuncSetAttribute(edge_kernel,
                         cudaFuncAttributeMaxDynamicSharedMemorySize, EDGE_DSM);

    node_kernel<<<NRES, 256>>>(X, C, node_aux, W_node, b_node, out);
    edge_kernel<<<dim3(NRES / (JTILE * TILES), NRES), 256, EDGE_DSM>>>(
        X, C, edge_aux, W_edge, b_edge, out);
}

// round 5
// speedup vs baseline: 1.0101x; 1.0101x over previous
#include <cuda_runtime.h>
#include <math.h>

#define NRES 768
#define DN   256
#define DE   128
#define EF   30
#define KP   32            // padded K for MMA
#define ETILE 32           // edges per MMA tile
#define TILES 8            // tiles per block (8*32 = 256 j per block)
typedef unsigned long long ull;

// ---- output layout (floats), concatenation of the reference tuple ----
#define NODE_OFF 0ULL
#define EDGE_OFF (768ULL * 256ULL)                       // 196608
#define IDX_OFF  (EDGE_OFF + 768ULL * 768ULL * 128ULL)   // 75694080
#define MI_OFF   (IDX_OFF + 768ULL * 768ULL)             // 76283904
#define MIJ_OFF  (MI_OFF + 768ULL)                       // 76284672

// scratch: per-residue frames R (row-major 3x3)
__device__ float g_R[NRES * 9];

__device__ __forceinline__ float3 ld3(const float* p) { return make_float3(p[0], p[1], p[2]); }
__device__ __forceinline__ float3 vsub(float3 a, float3 b) { return make_float3(a.x - b.x, a.y - b.y, a.z - b.z); }
__device__ __forceinline__ float  vdot(float3 a, float3 b) { return a.x * b.x + a.y * b.y + a.z * b.z; }
__device__ __forceinline__ float3 vcross(float3 a, float3 b) {
    return make_float3(a.y * b.z - a.z * b.y, a.z * b.x - a.x * b.z, a.x * b.y - a.y * b.x);
}
__device__ __forceinline__ float  vnorm(float3 a) { return sqrtf(vdot(a, a) + 1e-8f); }
__device__ __forceinline__ float3 vunit(float3 a) { float r = 1.0f / vnorm(a); return make_float3(a.x * r, a.y * r, a.z * r); }

// tf32 round (rna) -> fp32 bit pattern with low mantissa cleared
__device__ __forceinline__ unsigned tf32r(float x) {
    unsigned r; asm("cvt.rna.tf32.f32 %0, %1;" : "=r"(r) : "f"(x)); return r;
}

// m16n8k8 tf32 MMA, D += A*B
__device__ __forceinline__ void mma_tf32(float d[4], const unsigned a[4], const unsigned b[2]) {
    asm volatile(
        "mma.sync.aligned.m16n8k8.row.col.f32.tf32.tf32.f32 "
        "{%0,%1,%2,%3}, {%4,%5,%6,%7}, {%8,%9}, {%0,%1,%2,%3};"
        : "+f"(d[0]), "+f"(d[1]), "+f"(d[2]), "+f"(d[3])
        : "r"(a[0]), "r"(a[1]), "r"(a[2]), "r"(a[3]), "r"(b[0]), "r"(b[1]));
}

// ============================================================================
// Node kernel (tiny)
// ============================================================================
__global__ void __launch_bounds__(256) node_kernel(
    const float* __restrict__ X, const int* __restrict__ C,
    const float* __restrict__ aux, const float* __restrict__ Wn,
    const float* __restrict__ bn, float* __restrict__ out)
{
    __shared__ float sfeat[7];
    __shared__ float smask;
    const int n = blockIdx.x;

    if (threadIdx.x == 0) {
        const float* xp = X + n * 12;
        float3 Na = ld3(xp), Ca = ld3(xp + 3), Cc = ld3(xp + 6), Ox = ld3(xp + 9);

        float d1 = logf(vnorm(vsub(Ca, Na)) + 0.001f);
        float d2 = logf(vnorm(vsub(Cc, Ca)) + 0.001f);
        float d3 = logf(vnorm(vsub(Ox, Cc)) + 0.001f);
        float a1 = vdot(vunit(vsub(Na, Ca)), vunit(vsub(Cc, Ca)));
        float a2 = vdot(vunit(vsub(Ca, Cc)), vunit(vsub(Ox, Cc)));

        float3 b0 = vsub(Ca, Na), b1 = vsub(Cc, Ca), b2 = vsub(Ox, Cc);
        float3 n1 = vcross(b0, b1), n2 = vcross(b1, b2);
        float3 ub1 = vunit(b1);
        float3 m1 = vcross(n1, ub1);
        float xx = vdot(n1, n2), yy = vdot(m1, n2);
        float r = sqrtf(xx * xx + yy * yy + 1e-8f);

        sfeat[0] = d1; sfeat[1] = d2; sfeat[2] = d3;
        sfeat[3] = a1; sfeat[4] = a2;
        sfeat[5] = yy / r; sfeat[6] = xx / r;

        float mi = (C[n] > 0) ? 1.0f : 0.0f;
        smask = mi;
        out[MI_OFF + n] = mi;

        float3 e1 = ub1;
        float3 v  = vunit(vsub(Na, Ca));
        float d  = vdot(v, e1);
        float3 w = make_float3(v.x - d * e1.x, v.y - d * e1.y, v.z - d * e1.z);
        float3 e2 = vunit(w);
        float3 e3 = vcross(e1, e2);
        float* rp = g_R + n * 9;
        rp[0] = e1.x; rp[1] = e1.y; rp[2] = e1.z;
        rp[3] = e2.x; rp[4] = e2.y; rp[5] = e2.z;
        rp[6] = e3.x; rp[7] = e3.y; rp[8] = e3.z;
    }
    __syncthreads();

    const int c = threadIdx.x;
    float acc = bn[c];
#pragma unroll
    for (int k = 0; k < 7; k++) acc = fmaf(sfeat[k], Wn[k * DN + c], acc);
    float mi = smask;
    out[NODE_OFF + (size_t)n * DN + c] = mi * (acc + aux[(size_t)n * DN + c]);
}

__device__ __forceinline__ void stsplit(unsigned* h, unsigned* l, int idx, float v) {
    unsigned hi = tf32r(v);
    h[idx] = hi;
    l[idx] = tf32r(v - __uint_as_float(hi));
}

// ============================================================================
// Edge kernel: 32-edge MMA tiles (3xTF32), 4 blocks/SM for latency hiding.
// Phase 1: 8 threads per edge. Phase 2: warp patch 16 edges x 32 channels.
// ============================================================================
__global__ void __launch_bounds__(256, 4) edge_kernel(
    const float* __restrict__ X, const int* __restrict__ C,
    const float* __restrict__ aux, const float* __restrict__ We,
    const float* __restrict__ be, float* __restrict__ out)
{
    extern __shared__ __align__(16) unsigned char dsm[];
    unsigned* sAh = (unsigned*)dsm;                 // [32][36]
    unsigned* sAl = sAh + ETILE * 36;               // [32][36]
    unsigned* sBh = sAl + ETILE * 36;               // [128][36]  (c-major)
    unsigned* sBl = sBh + 128 * 36;                 // [128][36]
    float*    sb   = (float*)(sBl + 128 * 36);      // [128]
    float*    smij = sb + DE;                       // [32]

    __shared__ float sXi[12];
    __shared__ float sRi[9];
    __shared__ float sMiS;
    __shared__ int   sCiS;

    const int i   = blockIdx.y;
    const int tid = threadIdx.x;
    const int lane = tid & 31, warp = tid >> 5;
    const int gid = lane >> 2, tg = lane & 3;
    const int wm = warp & 1;       // 2 m-blocks of 16 edges
    const int wn = warp >> 1;      // 4 n-blocks of 32 channels

    // ---- one-time staging: split weights to tf32 hi/lo, transposed [c][k] ----
    for (int t = tid; t < KP * DE; t += 256) {
        int k = t >> 7, c = t & 127;
        float w = (k < EF) ? We[k * DE + c] : 0.0f;
        unsigned hi = tf32r(w);
        sBh[c * 36 + k] = hi;
        sBl[c * 36 + k] = tf32r(w - __uint_as_float(hi));
    }
    if (tid < DE) sb[tid] = be[tid];
    if (tid >= 128 && tid < 140) sXi[tid - 128] = X[i * 12 + (tid - 128)];
    if (tid >= 144 && tid < 153) sRi[tid - 144] = g_R[i * 9 + (tid - 144)];
    if (tid == 160) { int ci = C[i]; sCiS = ci; sMiS = (ci > 0) ? 1.0f : 0.0f; }
    // zero pad rows k=30,31 in A (never rewritten)
    if (tid < ETILE) {
        sAh[tid * 36 + 30] = 0u; sAh[tid * 36 + 31] = 0u;
        sAl[tid * 36 + 30] = 0u; sAl[tid * 36 + 31] = 0u;
    }
    __syncthreads();

    const int jbase0 = blockIdx.x * TILES * ETILE;

    for (int t = 0; t < TILES; t++) {
        const int jbase = jbase0 + t * ETILE;

        // ---- phase 1: 8 threads per edge compute the 30 features ----
        {
            const int e = tid >> 3;      // edge within tile (0..31)
            const int r = tid & 7;       // role
            const int j = jbase + e;

            if (r < 4) {
                // D row r (4 log-distances)
                float xj[12];
#pragma unroll
                for (int q = 0; q < 12; q++) xj[q] = X[j * 12 + q];
                const float xix = sXi[3 * r + 0], xiy = sXi[3 * r + 1], xiz = sXi[3 * r + 2];
#pragma unroll
                for (int q = 0; q < 4; q++) {
                    float dx = xix - xj[3 * q + 0];
                    float dy = xiy - xj[3 * q + 1];
                    float dz = xiz - xj[3 * q + 2];
                    float d2 = dx * dx + dy * dy + dz * dz;
                    stsplit(sAh, sAl, e * 36 + r * 4 + q, logf(sqrtf(d2 + 1e-8f) + 0.01f));
                }
            } else if (r < 7) {
                // Rrel row (r-4)
                const int p = r - 4;
                float rj[9];
#pragma unroll
                for (int q = 0; q < 9; q++) rj[q] = g_R[j * 9 + q];
                const float a0 = sRi[3 * p + 0], a1 = sRi[3 * p + 1], a2 = sRi[3 * p + 2];
#pragma unroll
                for (int q = 0; q < 3; q++) {
                    float v = a0 * rj[3 * q + 0] + a1 * rj[3 * q + 1] + a2 * rj[3 * q + 2];
                    stsplit(sAh, sAl, e * 36 + 16 + p * 3 + q, v);
                }
            } else {
                // trel, same_chain, sep, masks, side outputs
                float cax = X[j * 12 + 3], cay = X[j * 12 + 4], caz = X[j * 12 + 5];
                float dtx = cax - sXi[3], dty = cay - sXi[4], dtz = caz - sXi[5];
                float t0 = sRi[0] * dtx + sRi[1] * dty + sRi[2] * dtz;
                float t1 = sRi[3] * dtx + sRi[4] * dty + sRi[5] * dtz;
                float t2 = sRi[6] * dtx + sRi[7] * dty + sRi[8] * dtz;
                float rn = rsqrtf(t0 * t0 + t1 * t1 + t2 * t2 + 1e-8f);
                stsplit(sAh, sAl, e * 36 + 25, t0 * rn);
                stsplit(sAh, sAl, e * 36 + 26, t1 * rn);
                stsplit(sAh, sAl, e * 36 + 27, t2 * rn);
                int cj = C[j];
                stsplit(sAh, sAl, e * 36 + 28, (sCiS == cj) ? 1.0f : 0.0f);
                int dsep = j - i; dsep = min(32, max(-32, dsep));
                stsplit(sAh, sAl, e * 36 + 29, (float)dsep * (1.0f / 32.0f));

                float mij = sMiS * ((cj > 0) ? 1.0f : 0.0f);
                smij[e] = mij;
                out[IDX_OFF + (size_t)i * NRES + j] = (float)j;
                out[MIJ_OFF + (size_t)i * NRES + j] = mij;
            }
        }
        __syncthreads();

        // ---- phase 2: 3xTF32 MMA, warp patch = 16 edges x 32 channels ----
        float acc[4][4] = {};
#pragma unroll
        for (int kt = 0; kt < 4; kt++) {
            const int k0 = kt * 8 + tg;
            const int e = wm * 16 + gid;
            unsigned ah[4], al[4];
            ah[0] = sAh[e * 36 + k0];
            ah[1] = sAh[(e + 8) * 36 + k0];
            ah[2] = sAh[e * 36 + k0 + 4];
            ah[3] = sAh[(e + 8) * 36 + k0 + 4];
            al[0] = sAl[e * 36 + k0];
            al[1] = sAl[(e + 8) * 36 + k0];
            al[2] = sAl[e * 36 + k0 + 4];
            al[3] = sAl[(e + 8) * 36 + k0 + 4];
#pragma unroll
            for (int n = 0; n < 4; n++) {
                const int c = wn * 32 + n * 8 + gid;
                unsigned bh[2], bl[2];
                bh[0] = sBh[c * 36 + k0];
                bh[1] = sBh[c * 36 + k0 + 4];
                bl[0] = sBl[c * 36 + k0];
                bl[1] = sBl[c * 36 + k0 + 4];
                mma_tf32(acc[n], ah, bh);
                mma_tf32(acc[n], ah, bl);
                mma_tf32(acc[n], al, bh);
            }
        }

        // ---- epilogue: + bias + aux, * mij, streaming float2 stores ----
        {
            const int el0 = wm * 16 + gid;
            const int el1 = el0 + 8;
            const float mj0 = smij[el0];
            const float mj1 = smij[el1];
            const int j0 = jbase + el0, j1 = jbase + el1;
#pragma unroll
            for (int n = 0; n < 4; n++) {
                const int c = wn * 32 + n * 8 + 2 * tg;
                float2 bv = *(const float2*)&sb[c];
                size_t base0 = ((size_t)i * NRES + j0) * DE + c;
                size_t base1 = ((size_t)i * NRES + j1) * DE + c;
                float2 a0 = __ldcs((const float2*)&aux[base0]);
                float2 a1 = __ldcs((const float2*)&aux[base1]);
                float2 o0, o1;
                o0.x = mj0 * (acc[n][0] + bv.x + a0.x);
                o0.y = mj0 * (acc[n][1] + bv.y + a0.y);
                o1.x = mj1 * (acc[n][2] + bv.x + a1.x);
                o1.y = mj1 * (acc[n][3] + bv.y + a1.y);
                __stcs((float2*)&out[EDGE_OFF + base0], o0);
                __stcs((float2*)&out[EDGE_OFF + base1], o1);
            }
        }
        __syncthreads();   // protect sA / smij before next tile
    }
}

#define EDGE_DSM ((2 * ETILE * 36 + 2 * 128 * 36) * 4 + (DE + ETILE) * 4)

extern "C" void kernel_launch(void* const* d_in, const int* in_sizes, int n_in,
                              void* d_out, int out_size)
{
    const float* X        = (const float*)d_in[0];
    const int*   C        = (const int*)  d_in[1];
    const float* node_aux = (const float*)d_in[2];
    const float* edge_aux = (const float*)d_in[3];
    const float* W_node   = (const float*)d_in[4];
    const float* b_node   = (const float*)d_in[5];
    const float* W_edge   = (const float*)d_in[6];
    const float* b_edge   = (const float*)d_in[7];
    float* out = (float*)d_out;

    cudaFuncSetAttribute(edge_kernel,
                         cudaFuncAttributeMaxDynamicSharedMemorySize, EDGE_DSM);

    node_kernel<<<NRES, 256>>>(X, C, node_aux, W_node, b_node, out);
    edge_kernel<<<dim3(NRES / (ETILE * TILES), NRES), 256, EDGE_DSM>>>(
        X, C, edge_aux, W_edge, b_edge, out);
}

// round 6
// speedup vs baseline: 1.0552x; 1.0447x over previous
#include <cuda_runtime.h>
#include <math.h>

#define NRES 768
#define DN   256
#define DE   128
#define EF   30
#define ETILE 32           // edges per MMA tile
#define TILES 8            // tiles per block (8*32 = 256 j per block)

// ---- output layout (floats), concatenation of the reference tuple ----
#define NODE_OFF 0ULL
#define EDGE_OFF (768ULL * 256ULL)                       // 196608
#define IDX_OFF  (EDGE_OFF + 768ULL * 768ULL * 128ULL)   // 75694080
#define MI_OFF   (IDX_OFF + 768ULL * 768ULL)             // 76283904
#define MIJ_OFF  (MI_OFF + 768ULL)                       // 76284672

// scratch: per-residue frames R (row-major 3x3)
__device__ float g_R[NRES * 9];

__device__ __forceinline__ float3 ld3(const float* p) { return make_float3(p[0], p[1], p[2]); }
__device__ __forceinline__ float3 vsub(float3 a, float3 b) { return make_float3(a.x - b.x, a.y - b.y, a.z - b.z); }
__device__ __forceinline__ float  vdot(float3 a, float3 b) { return a.x * b.x + a.y * b.y + a.z * b.z; }
__device__ __forceinline__ float3 vcross(float3 a, float3 b) {
    return make_float3(a.y * b.z - a.z * b.y, a.z * b.x - a.x * b.z, a.x * b.y - a.y * b.x);
}
__device__ __forceinline__ float  vnorm(float3 a) { return sqrtf(vdot(a, a) + 1e-8f); }
__device__ __forceinline__ float3 vunit(float3 a) { float r = 1.0f / vnorm(a); return make_float3(a.x * r, a.y * r, a.z * r); }

// tf32 round (rna) -> fp32 bit pattern with low mantissa cleared
__device__ __forceinline__ unsigned tf32r(float x) {
    unsigned r; asm("cvt.rna.tf32.f32 %0, %1;" : "=r"(r) : "f"(x)); return r;
}

// m16n8k8 tf32 MMA, D += A*B
__device__ __forceinline__ void mma_tf32(float d[4], const unsigned a[4], const unsigned b[2]) {
    asm volatile(
        "mma.sync.aligned.m16n8k8.row.col.f32.tf32.tf32.f32 "
        "{%0,%1,%2,%3}, {%4,%5,%6,%7}, {%8,%9}, {%0,%1,%2,%3};"
        : "+f"(d[0]), "+f"(d[1]), "+f"(d[2]), "+f"(d[3])
        : "r"(a[0]), "r"(a[1]), "r"(a[2]), "r"(a[3]), "r"(b[0]), "r"(b[1]));
}

// ============================================================================
// Node kernel (tiny)
// ============================================================================
__global__ void __launch_bounds__(256) node_kernel(
    const float* __restrict__ X, const int* __restrict__ C,
    const float* __restrict__ aux, const float* __restrict__ Wn,
    const float* __restrict__ bn, float* __restrict__ out)
{
    __shared__ float sfeat[7];
    __shared__ float smask;
    const int n = blockIdx.x;

    if (threadIdx.x == 0) {
        const float* xp = X + n * 12;
        float3 Na = ld3(xp), Ca = ld3(xp + 3), Cc = ld3(xp + 6), Ox = ld3(xp + 9);

        float d1 = logf(vnorm(vsub(Ca, Na)) + 0.001f);
        float d2 = logf(vnorm(vsub(Cc, Ca)) + 0.001f);
        float d3 = logf(vnorm(vsub(Ox, Cc)) + 0.001f);
        float a1 = vdot(vunit(vsub(Na, Ca)), vunit(vsub(Cc, Ca)));
        float a2 = vdot(vunit(vsub(Ca, Cc)), vunit(vsub(Ox, Cc)));

        float3 b0 = vsub(Ca, Na), b1 = vsub(Cc, Ca), b2 = vsub(Ox, Cc);
        float3 n1 = vcross(b0, b1), n2 = vcross(b1, b2);
        float3 ub1 = vunit(b1);
        float3 m1 = vcross(n1, ub1);
        float xx = vdot(n1, n2), yy = vdot(m1, n2);
        float r = sqrtf(xx * xx + yy * yy + 1e-8f);

        sfeat[0] = d1; sfeat[1] = d2; sfeat[2] = d3;
        sfeat[3] = a1; sfeat[4] = a2;
        sfeat[5] = yy / r; sfeat[6] = xx / r;

        float mi = (C[n] > 0) ? 1.0f : 0.0f;
        smask = mi;
        out[MI_OFF + n] = mi;

        float3 e1 = ub1;
        float3 v  = vunit(vsub(Na, Ca));
        float d  = vdot(v, e1);
        float3 w = make_float3(v.x - d * e1.x, v.y - d * e1.y, v.z - d * e1.z);
        float3 e2 = vunit(w);
        float3 e3 = vcross(e1, e2);
        float* rp = g_R + n * 9;
        rp[0] = e1.x; rp[1] = e1.y; rp[2] = e1.z;
        rp[3] = e2.x; rp[4] = e2.y; rp[5] = e2.z;
        rp[6] = e3.x; rp[7] = e3.y; rp[8] = e3.z;
    }
    __syncthreads();

    const int c = threadIdx.x;
    float acc = bn[c];
#pragma unroll
    for (int k = 0; k < 7; k++) acc = fmaf(sfeat[k], Wn[k * DN + c], acc);
    float mi = smask;
    out[NODE_OFF + (size_t)n * DN + c] = mi * (acc + aux[(size_t)n * DN + c]);
}

// A smem layout: [e][kt][tg] -> 4 words (ah_k0, al_k0, ah_k0+4, al_k0+4).
// index in words for feature k of edge e:
//   kt = k>>3, tg = k&3, off = ((k&7)>=4) ? 2 : 0
//   word = (e*16 + kt*4 + tg)*4 + off (hi), +1 (lo)
__device__ __forceinline__ void astore(unsigned* sA, int e, int k, float v) {
    int idx = ((e << 4) + ((k >> 3) << 2) + (k & 3)) * 4 + (((k & 7) >= 4) ? 2 : 0);
    unsigned hi = tf32r(v);
    sA[idx] = hi;
    sA[idx + 1] = tf32r(v - __uint_as_float(hi));
}

// ============================================================================
// Edge kernel: 3xTF32 MMA with B (weights) held in REGISTERS, A in smem in
// fragment-native layout (LDS.128), channel-permuted float4 epilogue.
// ============================================================================
__global__ void __launch_bounds__(256, 2) edge_kernel(
    const float* __restrict__ X, const int* __restrict__ C,
    const float* __restrict__ aux, const float* __restrict__ We,
    const float* __restrict__ be, float* __restrict__ out)
{
    __shared__ __align__(16) unsigned sA[ETILE * 16 * 4];   // 8 KB
    __shared__ __align__(16) float sb[DE];
    __shared__ float smij[ETILE];
    __shared__ float sXi[12];
    __shared__ float sRi[9];
    __shared__ float sMiS;
    __shared__ int   sCiS;

    const int i   = blockIdx.y;
    const int tid = threadIdx.x;
    const int lane = tid & 31, warp = tid >> 5;
    const int gid = lane >> 2, tg = lane & 3;
    const int wm = warp & 1;       // 2 m-blocks of 16 edges
    const int wn = warp >> 1;      // 4 n-blocks of 32 channels

    // ---- B fragments into registers (one-time). chan permutation:
    //      chan(wn, n, nn) = wn*32 + (nn>>1)*8 + n*2 + (nn&1), nn = mma col.
    //      B fragment: lane provides col nn = gid, rows k = kt*8+tg, +4.
    unsigned Bh[4][4][2], Bl[4][4][2];
    {
        const int chan_base = wn * 32 + (gid >> 1) * 8 + (gid & 1);
#pragma unroll
        for (int kt = 0; kt < 4; kt++)
#pragma unroll
            for (int n = 0; n < 4; n++)
#pragma unroll
                for (int s = 0; s < 2; s++) {
                    int k = kt * 8 + tg + s * 4;
                    float w = (k < EF) ? We[k * DE + chan_base + n * 2] : 0.0f;
                    unsigned hi = tf32r(w);
                    Bh[kt][n][s] = hi;
                    Bl[kt][n][s] = tf32r(w - __uint_as_float(hi));
                }
    }

    // ---- one-time staging ----
    if (tid < DE) sb[tid] = be[tid];
    if (tid >= 128 && tid < 140) sXi[tid - 128] = X[i * 12 + (tid - 128)];
    if (tid >= 144 && tid < 153) sRi[tid - 144] = g_R[i * 9 + (tid - 144)];
    if (tid == 160) { int ci = C[i]; sCiS = ci; sMiS = (ci > 0) ? 1.0f : 0.0f; }
    // zero pad words for k=30,31 (kt=3, tg=2/3, off=2): never rewritten
    if (tid < ETILE) {
        sA[(tid * 16 + 14) * 4 + 2] = 0u; sA[(tid * 16 + 14) * 4 + 3] = 0u;
        sA[(tid * 16 + 15) * 4 + 2] = 0u; sA[(tid * 16 + 15) * 4 + 3] = 0u;
    }
    __syncthreads();

    const int jbase0 = blockIdx.x * TILES * ETILE;

    for (int t = 0; t < TILES; t++) {
        const int jbase = jbase0 + t * ETILE;

        // ---- phase 1: 8 threads per edge compute the 30 features ----
        {
            const int e = tid >> 3;      // edge within tile (0..31)
            const int r = tid & 7;       // role
            const int j = jbase + e;

            if (r < 4) {
                float xj[12];
#pragma unroll
                for (int q = 0; q < 12; q++) xj[q] = X[j * 12 + q];
                const float xix = sXi[3 * r + 0], xiy = sXi[3 * r + 1], xiz = sXi[3 * r + 2];
#pragma unroll
                for (int q = 0; q < 4; q++) {
                    float dx = xix - xj[3 * q + 0];
                    float dy = xiy - xj[3 * q + 1];
                    float dz = xiz - xj[3 * q + 2];
                    float d2 = dx * dx + dy * dy + dz * dz;
                    astore(sA, e, r * 4 + q, logf(sqrtf(d2 + 1e-8f) + 0.01f));
                }
            } else if (r < 7) {
                const int p = r - 4;
                float rj[9];
#pragma unroll
                for (int q = 0; q < 9; q++) rj[q] = g_R[j * 9 + q];
                const float a0 = sRi[3 * p + 0], a1 = sRi[3 * p + 1], a2 = sRi[3 * p + 2];
#pragma unroll
                for (int q = 0; q < 3; q++) {
                    float v = a0 * rj[3 * q + 0] + a1 * rj[3 * q + 1] + a2 * rj[3 * q + 2];
                    astore(sA, e, 16 + p * 3 + q, v);
                }
            } else {
                float cax = X[j * 12 + 3], cay = X[j * 12 + 4], caz = X[j * 12 + 5];
                float dtx = cax - sXi[3], dty = cay - sXi[4], dtz = caz - sXi[5];
                float t0 = sRi[0] * dtx + sRi[1] * dty + sRi[2] * dtz;
                float t1 = sRi[3] * dtx + sRi[4] * dty + sRi[5] * dtz;
                float t2 = sRi[6] * dtx + sRi[7] * dty + sRi[8] * dtz;
                float rn = rsqrtf(t0 * t0 + t1 * t1 + t2 * t2 + 1e-8f);
                astore(sA, e, 25, t0 * rn);
                astore(sA, e, 26, t1 * rn);
                astore(sA, e, 27, t2 * rn);
                int cj = C[j];
                astore(sA, e, 28, (sCiS == cj) ? 1.0f : 0.0f);
                int dsep = j - i; dsep = min(32, max(-32, dsep));
                astore(sA, e, 29, (float)dsep * (1.0f / 32.0f));

                float mij = sMiS * ((cj > 0) ? 1.0f : 0.0f);
                smij[e] = mij;
                out[IDX_OFF + (size_t)i * NRES + j] = (float)j;
                out[MIJ_OFF + (size_t)i * NRES + j] = mij;
            }
        }
        __syncthreads();

        // ---- phase 2: MMA. Warp patch = 16 edges x 32 channels. B in regs. ----
        float acc[4][4] = {};
        const int e0 = wm * 16 + gid;
#pragma unroll
        for (int kt = 0; kt < 4; kt++) {
            const unsigned* p0 = &sA[(e0 * 16 + kt * 4 + tg) * 4];
            uint4 q0 = *(const uint4*)p0;            // row e0:  ah_k0, al_k0, ah_k0+4, al_k0+4
            uint4 q1 = *(const uint4*)(p0 + 8 * 64); // row e0+8
            unsigned ah[4] = {q0.x, q1.x, q0.z, q1.z};
            unsigned al[4] = {q0.y, q1.y, q0.w, q1.w};
#pragma unroll
            for (int n = 0; n < 4; n++) {
                mma_tf32(acc[n], ah, Bh[kt][n]);
                mma_tf32(acc[n], ah, Bl[kt][n]);
                mma_tf32(acc[n], al, Bh[kt][n]);
            }
        }

        // ---- epilogue: lane owns 8 contiguous channels c0..c0+7 ----
        {
            const int c0 = wn * 32 + tg * 8;
            const int el0 = wm * 16 + gid, el1 = el0 + 8;
            const float mj0 = smij[el0], mj1 = smij[el1];
            const int j0 = jbase + el0, j1 = jbase + el1;
            float4 bv0 = *(const float4*)&sb[c0];
            float4 bv1 = *(const float4*)&sb[c0 + 4];
            size_t base0 = ((size_t)i * NRES + j0) * DE + c0;
            size_t base1 = ((size_t)i * NRES + j1) * DE + c0;
            float4 x0 = __ldcs((const float4*)&aux[base0]);
            float4 x1 = __ldcs((const float4*)&aux[base0 + 4]);
            float4 y0 = __ldcs((const float4*)&aux[base1]);
            float4 y1 = __ldcs((const float4*)&aux[base1 + 4]);
            float4 o;
            o.x = mj0 * (acc[0][0] + bv0.x + x0.x);
            o.y = mj0 * (acc[0][1] + bv0.y + x0.y);
            o.z = mj0 * (acc[1][0] + bv0.z + x0.z);
            o.w = mj0 * (acc[1][1] + bv0.w + x0.w);
            __stcs((float4*)&out[EDGE_OFF + base0], o);
            o.x = mj0 * (acc[2][0] + bv1.x + x1.x);
            o.y = mj0 * (acc[2][1] + bv1.y + x1.y);
            o.z = mj0 * (acc[3][0] + bv1.z + x1.z);
            o.w = mj0 * (acc[3][1] + bv1.w + x1.w);
            __stcs((float4*)&out[EDGE_OFF + base0 + 4], o);
            o.x = mj1 * (acc[0][2] + bv0.x + y0.x);
            o.y = mj1 * (acc[0][3] + bv0.y + y0.y);
            o.z = mj1 * (acc[1][2] + bv0.z + y0.z);
            o.w = mj1 * (acc[1][3] + bv0.w + y0.w);
            __stcs((float4*)&out[EDGE_OFF + base1], o);
            o.x = mj1 * (acc[2][2] + bv1.x + y1.x);
            o.y = mj1 * (acc[2][3] + bv1.y + y1.y);
            o.z = mj1 * (acc[3][2] + bv1.z + y1.z);
            o.w = mj1 * (acc[3][3] + bv1.w + y1.w);
            __stcs((float4*)&out[EDGE_OFF + base1 + 4], o);
        }
        __syncthreads();   // protect sA / smij before next tile
    }
}

extern "C" void kernel_launch(void* const* d_in, const int* in_sizes, int n_in,
                              void* d_out, int out_size)
{
    const float* X        = (const float*)d_in[0];
    const int*   C        = (const int*)  d_in[1];
    const float* node_aux = (const float*)d_in[2];
    const float* edge_aux = (const float*)d_in[3];
    const float* W_node   = (const float*)d_in[4];
    const float* b_node   = (const float*)d_in[5];
    const float* W_edge   = (const float*)d_in[6];
    const float* b_edge   = (const float*)d_in[7];
    float* out = (float*)d_out;

    node_kernel<<<NRES, 256>>>(X, C, node_aux, W_node, b_node, out);
    edge_kernel<<<dim3(NRES / (ETILE * TILES), NRES), 256>>>(
        X, C, edge_aux, W_edge, b_edge, out);
}

// round 7
// speedup vs baseline: 1.4056x; 1.3320x over previous
#include <cuda_runtime.h>
#include <math.h>

#define NRES 768
#define DN   256
#define DE   128
#define EF   30
#define NT   24            // residue tiles (768/32)
#define TS   32            // tile size
#define NSUB 16            // sub-iterations per block (2 i-rows each)
#define NPAIRS 300         // NT*(NT+1)/2

// ---- output layout (floats), concatenation of the reference tuple ----
#define NODE_OFF 0ULL
#define EDGE_OFF (768ULL * 256ULL)                       // 196608
#define IDX_OFF  (EDGE_OFF + 768ULL * 768ULL * 128ULL)   // 75694080
#define MI_OFF   (IDX_OFF + 768ULL * 768ULL)             // 76283904
#define MIJ_OFF  (MI_OFF + 768ULL)                       // 76284672

// scratch: per-residue frames R (row-major 3x3)
__device__ float g_R[NRES * 9];

__device__ __forceinline__ float3 ld3(const float* p) { return make_float3(p[0], p[1], p[2]); }
__device__ __forceinline__ float3 vsub(float3 a, float3 b) { return make_float3(a.x - b.x, a.y - b.y, a.z - b.z); }
__device__ __forceinline__ float  vdot(float3 a, float3 b) { return a.x * b.x + a.y * b.y + a.z * b.z; }
__device__ __forceinline__ float3 vcross(float3 a, float3 b) {
    return make_float3(a.y * b.z - a.z * b.y, a.z * b.x - a.x * b.z, a.x * b.y - a.y * b.x);
}
__device__ __forceinline__ float  vnorm(float3 a) { return sqrtf(vdot(a, a) + 1e-8f); }
__device__ __forceinline__ float3 vunit(float3 a) { float r = 1.0f / vnorm(a); return make_float3(a.x * r, a.y * r, a.z * r); }

// tf32 round (rna) -> fp32 bit pattern with low mantissa cleared
__device__ __forceinline__ unsigned tf32r(float x) {
    unsigned r; asm("cvt.rna.tf32.f32 %0, %1;" : "=r"(r) : "f"(x)); return r;
}

// m16n8k8 tf32 MMA, D += A*B
__device__ __forceinline__ void mma_tf32(float d[4], const unsigned a[4], const unsigned b[2]) {
    asm volatile(
        "mma.sync.aligned.m16n8k8.row.col.f32.tf32.tf32.f32 "
        "{%0,%1,%2,%3}, {%4,%5,%6,%7}, {%8,%9}, {%0,%1,%2,%3};"
        : "+f"(d[0]), "+f"(d[1]), "+f"(d[2]), "+f"(d[3])
        : "r"(a[0]), "r"(a[1]), "r"(a[2]), "r"(a[3]), "r"(b[0]), "r"(b[1]));
}

// ============================================================================
// Node kernel (tiny)
// ============================================================================
__global__ void __launch_bounds__(256) node_kernel(
    const float* __restrict__ X, const int* __restrict__ C,
    const float* __restrict__ aux, const float* __restrict__ Wn,
    const float* __restrict__ bn, float* __restrict__ out)
{
    __shared__ float sfeat[7];
    __shared__ float smask;
    const int n = blockIdx.x;

    if (threadIdx.x == 0) {
        const float* xp = X + n * 12;
        float3 Na = ld3(xp), Ca = ld3(xp + 3), Cc = ld3(xp + 6), Ox = ld3(xp + 9);

        float d1 = logf(vnorm(vsub(Ca, Na)) + 0.001f);
        float d2 = logf(vnorm(vsub(Cc, Ca)) + 0.001f);
        float d3 = logf(vnorm(vsub(Ox, Cc)) + 0.001f);
        float a1 = vdot(vunit(vsub(Na, Ca)), vunit(vsub(Cc, Ca)));
        float a2 = vdot(vunit(vsub(Ca, Cc)), vunit(vsub(Ox, Cc)));

        float3 b0 = vsub(Ca, Na), b1 = vsub(Cc, Ca), b2 = vsub(Ox, Cc);
        float3 n1 = vcross(b0, b1), n2 = vcross(b1, b2);
        float3 ub1 = vunit(b1);
        float3 m1 = vcross(n1, ub1);
        float xx = vdot(n1, n2), yy = vdot(m1, n2);
        float r = sqrtf(xx * xx + yy * yy + 1e-8f);

        sfeat[0] = d1; sfeat[1] = d2; sfeat[2] = d3;
        sfeat[3] = a1; sfeat[4] = a2;
        sfeat[5] = yy / r; sfeat[6] = xx / r;

        float mi = (C[n] > 0) ? 1.0f : 0.0f;
        smask = mi;
        out[MI_OFF + n] = mi;

        float3 e1 = ub1;
        float3 v  = vunit(vsub(Na, Ca));
        float d  = vdot(v, e1);
        float3 w = make_float3(v.x - d * e1.x, v.y - d * e1.y, v.z - d * e1.z);
        float3 e2 = vunit(w);
        float3 e3 = vcross(e1, e2);
        float* rp = g_R + n * 9;
        rp[0] = e1.x; rp[1] = e1.y; rp[2] = e1.z;
        rp[3] = e2.x; rp[4] = e2.y; rp[5] = e2.z;
        rp[6] = e3.x; rp[7] = e3.y; rp[8] = e3.z;
    }
    __syncthreads();

    const int c = threadIdx.x;
    float acc = bn[c];
#pragma unroll
    for (int k = 0; k < 7; k++) acc = fmaf(sfeat[k], Wn[k * DN + c], acc);
    float mi = smask;
    out[NODE_OFF + (size_t)n * DN + c] = mi * (acc + aux[(size_t)n * DN + c]);
}

// A smem layout (fragment-native, per row): [kt][tg] -> 4 words
//   (ah_k, al_k, ah_k+4, al_k+4); k = kt*8 + tg (+4)
__device__ __forceinline__ void astore(unsigned* sA, int e, int k, float v) {
    int idx = ((e << 4) + ((k >> 3) << 2) + (k & 3)) * 4 + (((k & 7) >= 4) ? 2 : 0);
    unsigned hi = tf32r(v);
    uint2 w; w.x = hi; w.y = tf32r(v - __uint_as_float(hi));
    *(uint2*)&sA[idx] = w;
}

// ============================================================================
// Edge kernel: symmetric tile-pair blocks. Geometry (sqrt/log/dots) computed
// once per unordered pair, features emitted for BOTH edge directions.
// 3xTF32 MMA with weights in registers (R6 layout).
// ============================================================================
__global__ void __launch_bounds__(256, 2) edge_kernel(
    const float* __restrict__ X, const int* __restrict__ C,
    const float* __restrict__ aux, const float* __restrict__ We,
    const float* __restrict__ be, float* __restrict__ out)
{
    __shared__ __align__(16) unsigned sA[128 * 64];   // 32 KB: 128 feature rows
    __shared__ float sXi[TS * 12], sXj[TS * 12];
    __shared__ float sRi[TS * 9],  sRj[TS * 9];
    __shared__ int   sCi[TS], sCj[TS];
    __shared__ float sb[DE];
    __shared__ float smij[128];
    __shared__ int   sIr[128], sJr[128];

    const int tid = threadIdx.x;
    const int lane = tid & 31, warp = tid >> 5;
    const int gid = lane >> 2, tg = lane & 3;
    const int wm = warp & 1;       // 2 m-blocks of 16 rows
    const int wn = warp >> 1;      // 4 n-blocks of 32 channels

    // ---- triangular decode: blockIdx.x -> (It, Jt), It <= Jt ----
    int It = 0, rem = blockIdx.x, len = NT;
    while (rem >= len) { rem -= len; It++; len--; }
    const int Jt = It + rem;
    const bool isDiag = (It == Jt);

    // ---- B fragments into registers (channel permutation as R6) ----
    unsigned Bh[4][4][2], Bl[4][4][2];
    {
        const int chan_base = wn * 32 + (gid >> 1) * 8 + (gid & 1);
#pragma unroll
        for (int kt = 0; kt < 4; kt++)
#pragma unroll
            for (int n = 0; n < 4; n++)
#pragma unroll
                for (int s = 0; s < 2; s++) {
                    int k = kt * 8 + tg + s * 4;
                    float w = (k < EF) ? We[k * DE + chan_base + n * 2] : 0.0f;
                    unsigned hi = tf32r(w);
                    Bh[kt][n][s] = hi;
                    Bl[kt][n][s] = tf32r(w - __uint_as_float(hi));
                }
    }

    // ---- stage tile data ----
    for (int t = tid; t < TS * 12; t += 256) {
        sXi[t] = X[(It * TS) * 12 + t];
        sXj[t] = X[(Jt * TS) * 12 + t];
    }
    for (int t = tid; t < TS * 9; t += 256) {
        sRi[t] = g_R[(It * TS) * 9 + t];
        sRj[t] = g_R[(Jt * TS) * 9 + t];
    }
    if (tid < TS) { sCi[tid] = C[It * TS + tid]; sCj[tid] = C[Jt * TS + tid]; }
    if (tid < DE) sb[tid] = be[tid];
    if (tid < 128) {  // zero pad words for k=30,31 (never rewritten)
        sA[(tid * 16 + 14) * 4 + 2] = 0u; sA[(tid * 16 + 14) * 4 + 3] = 0u;
        sA[(tid * 16 + 15) * 4 + 2] = 0u; sA[(tid * 16 + 15) * 4 + 3] = 0u;
    }
    __syncthreads();

    for (int sub = 0; sub < NSUB; sub++) {
        // ---- phase 1: 64 pairs (2 i-rows x 32 j), 4 threads/pair ----
        {
            const int p = tid >> 2, r = tid & 3;
            const int il = p >> 5, jl = p & 31;
            const int iL = sub * 2 + il;
            const int iG = It * TS + iL, jG = Jt * TS + jl;
            const int frow = il * 32 + jl, rrow = 64 + frow;

            // D: this thread handles i-atom r vs all 4 j-atoms (shared both dirs)
            const float xpx = sXi[iL * 12 + r * 3 + 0];
            const float xpy = sXi[iL * 12 + r * 3 + 1];
            const float xpz = sXi[iL * 12 + r * 3 + 2];
#pragma unroll
            for (int q = 0; q < 4; q++) {
                float dx = xpx - sXj[jl * 12 + q * 3 + 0];
                float dy = xpy - sXj[jl * 12 + q * 3 + 1];
                float dz = xpz - sXj[jl * 12 + q * 3 + 2];
                float d2 = dx * dx + dy * dy + dz * dz;
                float v = __logf(sqrtf(d2 + 1e-8f) + 0.01f);
                astore(sA, frow, r * 4 + q, v);
                if (!isDiag) astore(sA, rrow, q * 4 + r, v);
            }

            if (r < 3) {
                // Rrel row r (rev = transpose, no recompute)
                const float a0 = sRi[iL * 9 + r * 3 + 0];
                const float a1 = sRi[iL * 9 + r * 3 + 1];
                const float a2 = sRi[iL * 9 + r * 3 + 2];
#pragma unroll
                for (int q = 0; q < 3; q++) {
                    float v = a0 * sRj[jl * 9 + q * 3 + 0]
                            + a1 * sRj[jl * 9 + q * 3 + 1]
                            + a2 * sRj[jl * 9 + q * 3 + 2];
                    astore(sA, frow, 16 + r * 3 + q, v);
                    if (!isDiag) astore(sA, rrow, 16 + q * 3 + r, v);
                }
            } else {
                // trel (shared norm: ||R dt|| = ||dt||), chain, sep, masks
                float dtx = sXj[jl * 12 + 3] - sXi[iL * 12 + 3];
                float dty = sXj[jl * 12 + 4] - sXi[iL * 12 + 4];
                float dtz = sXj[jl * 12 + 5] - sXi[iL * 12 + 5];
                float rn = rsqrtf(dtx * dtx + dty * dty + dtz * dtz + 1e-8f);
#pragma unroll
                for (int q = 0; q < 3; q++) {
                    float tf = (sRi[iL * 9 + q * 3 + 0] * dtx
                              + sRi[iL * 9 + q * 3 + 1] * dty
                              + sRi[iL * 9 + q * 3 + 2] * dtz) * rn;
                    astore(sA, frow, 25 + q, tf);
                    if (!isDiag) {
                        float tr = -(sRj[jl * 9 + q * 3 + 0] * dtx
                                   + sRj[jl * 9 + q * 3 + 1] * dty
                                   + sRj[jl * 9 + q * 3 + 2] * dtz) * rn;
                        astore(sA, rrow, 25 + q, tr);
                    }
                }
                int ci = sCi[iL], cj = sCj[jl];
                float sc = (ci == cj) ? 1.0f : 0.0f;
                astore(sA, frow, 28, sc);
                int dsep = jG - iG; dsep = min(32, max(-32, dsep));
                float sepv = (float)dsep * (1.0f / 32.0f);
                astore(sA, frow, 29, sepv);
                float mij = (ci > 0 && cj > 0) ? 1.0f : 0.0f;
                smij[frow] = mij; sIr[frow] = iG; sJr[frow] = jG;
                out[IDX_OFF + (size_t)iG * NRES + jG] = (float)jG;
                out[MIJ_OFF + (size_t)iG * NRES + jG] = mij;
                if (!isDiag) {
                    astore(sA, rrow, 28, sc);
                    astore(sA, rrow, 29, -sepv);
                    smij[rrow] = mij; sIr[rrow] = jG; sJr[rrow] = iG;
                    out[IDX_OFF + (size_t)jG * NRES + iG] = (float)iG;
                    out[MIJ_OFF + (size_t)jG * NRES + iG] = mij;
                }
            }
        }
        __syncthreads();

        // ---- phase 2: MMA + epilogue over row-groups of 32 ----
        const int ngroups = isDiag ? 2 : 4;
        for (int g = 0; g < ngroups; g++) {
            float acc[4][4] = {};
            const int e0 = g * 32 + wm * 16 + gid;
#pragma unroll
            for (int kt = 0; kt < 4; kt++) {
                const unsigned* p0 = &sA[(e0 * 16 + kt * 4 + tg) * 4];
                uint4 q0 = *(const uint4*)p0;            // row e0
                uint4 q1 = *(const uint4*)(p0 + 8 * 64); // row e0+8
                unsigned ah[4] = {q0.x, q1.x, q0.z, q1.z};
                unsigned al[4] = {q0.y, q1.y, q0.w, q1.w};
#pragma unroll
                for (int n = 0; n < 4; n++) {
                    mma_tf32(acc[n], ah, Bh[kt][n]);
                    mma_tf32(acc[n], ah, Bl[kt][n]);
                    mma_tf32(acc[n], al, Bh[kt][n]);
                }
            }

            // epilogue: lane owns 8 contiguous channels
            const int c0 = wn * 32 + tg * 8;
            const int el0 = e0, el1 = e0 + 8;
            const float mj0 = smij[el0], mj1 = smij[el1];
            float4 bv0 = *(const float4*)&sb[c0];
            float4 bv1 = *(const float4*)&sb[c0 + 4];
            size_t base0 = ((size_t)sIr[el0] * NRES + sJr[el0]) * DE + c0;
            size_t base1 = ((size_t)sIr[el1] * NRES + sJr[el1]) * DE + c0;
            float4 x0 = __ldcs((const float4*)&aux[base0]);
            float4 x1 = __ldcs((const float4*)&aux[base0 + 4]);
            float4 y0 = __ldcs((const float4*)&aux[base1]);
            float4 y1 = __ldcs((const float4*)&aux[base1 + 4]);
            float4 o;
            o.x = mj0 * (acc[0][0] + bv0.x + x0.x);
            o.y = mj0 * (acc[0][1] + bv0.y + x0.y);
            o.z = mj0 * (acc[1][0] + bv0.z + x0.z);
            o.w = mj0 * (acc[1][1] + bv0.w + x0.w);
            __stcs((float4*)&out[EDGE_OFF + base0], o);
            o.x = mj0 * (acc[2][0] + bv1.x + x1.x);
            o.y = mj0 * (acc[2][1] + bv1.y + x1.y);
            o.z = mj0 * (acc[3][0] + bv1.z + x1.z);
            o.w = mj0 * (acc[3][1] + bv1.w + x1.w);
            __stcs((float4*)&out[EDGE_OFF + base0 + 4], o);
            o.x = mj1 * (acc[0][2] + bv0.x + y0.x);
            o.y = mj1 * (acc[0][3] + bv0.y + y0.y);
            o.z = mj1 * (acc[1][2] + bv0.z + y0.z);
            o.w = mj1 * (acc[1][3] + bv0.w + y0.w);
            __stcs((float4*)&out[EDGE_OFF + base1], o);
            o.x = mj1 * (acc[2][2] + bv1.x + y1.x);
            o.y = mj1 * (acc[2][3] + bv1.y + y1.y);
            o.z = mj1 * (acc[3][2] + bv1.z + y1.z);
            o.w = mj1 * (acc[3][3] + bv1.w + y1.w);
            __stcs((float4*)&out[EDGE_OFF + base1 + 4], o);
        }
        __syncthreads();   // protect sA / smij / sIr / sJr before next sub
    }
}

extern "C" void kernel_launch(void* const* d_in, const int* in_sizes, int n_in,
                              void* d_out, int out_size)
{
    const float* X        = (const float*)d_in[0];
    const int*   C        = (const int*)  d_in[1];
    const float* node_aux = (const float*)d_in[2];
    const float* edge_aux = (const float*)d_in[3];
    const float* W_node   = (const float*)d_in[4];
    const float* b_node   = (const float*)d_in[5];
    const float* W_edge   = (const float*)d_in[6];
    const float* b_edge   = (const float*)d_in[7];
    float* out = (float*)d_out;

    node_kernel<<<NRES, 256>>>(X, C, node_aux, W_node, b_node, out);
    edge_kernel<<<NPAIRS, 256>>>(X, C, edge_aux, W_edge, b_edge, out);
}